// round 16
// baseline (speedup 1.0000x reference)
#include <cuda_runtime.h>
#include <cuda_fp16.h>
#include <cstdint>

// Problem constants
#define E_EXP 16
#define DMODEL 1024
#define DFF 2048
#define TMAX 4096
#define LN_EPS 1e-5f

#define BK 32          // fp32 elements per K-chunk
#define RTOK 8         // tokens per router block
#define PGRID 304      // persistent CTAs (2 per SM x 152)

// ---------------- scratch (device globals) ------------------------------------
__device__ int   g_cnt[E_EXP];
__device__ int   g_list[E_EXP * TMAX];             // pid = token*2 + slot
__device__ int   g_tok_e[2 * TMAX];
__device__ float g_tok_c[2 * TMAX];
__device__ float g_Y[(size_t)2 * TMAX * DMODEL];   // [pid][D]

// work scheduler
__device__ int g_pair_e[512];
__device__ int g_pair_mt[512];
__device__ int g_npairs;
__device__ int g_wk1, g_wk2;

// fp16 tensors: activations split hi/lo, weights hi only
__device__ __align__(16) __half g_xh[(size_t)TMAX * DMODEL];
__device__ __align__(16) __half g_xl[(size_t)TMAX * DMODEL];
__device__ __align__(16) __half g_w1h[(size_t)E_EXP * DFF * DMODEL];
__device__ __align__(16) __half g_w3h[(size_t)E_EXP * DFF * DMODEL];
__device__ __align__(16) __half g_w2h[(size_t)E_EXP * DMODEL * DFF];
__device__ __align__(16) __half g_Hh[(size_t)2 * TMAX * DFF];
__device__ __align__(16) __half g_Hl[(size_t)2 * TMAX * DFF];

// ---------------- helpers -------------------------------------------------------
__device__ __forceinline__ uint32_t smem_u32(const void* p) {
    uint32_t a;
    asm("{ .reg .u64 t; cvta.to.shared.u64 t, %1; cvt.u32.u64 %0, t; }" : "=r"(a) : "l"(p));
    return a;
}

__device__ __forceinline__ void mma_f16(float* c, const uint32_t* a,
                                        uint32_t b0, uint32_t b1) {
    asm volatile(
        "mma.sync.aligned.m16n8k16.row.col.f32.f16.f16.f32 "
        "{%0,%1,%2,%3}, {%4,%5,%6,%7}, {%8,%9}, {%0,%1,%2,%3};\n"
        : "+f"(c[0]), "+f"(c[1]), "+f"(c[2]), "+f"(c[3])
        : "r"(a[0]), "r"(a[1]), "r"(a[2]), "r"(a[3]), "r"(b0), "r"(b1));
}

__device__ __forceinline__ void ldsm4(uint32_t* r, uint32_t a) {
    asm volatile("ldmatrix.sync.aligned.m8n8.x4.shared.b16 {%0,%1,%2,%3}, [%4];"
        : "=r"(r[0]), "=r"(r[1]), "=r"(r[2]), "=r"(r[3]) : "r"(a));
}

__device__ __forceinline__ uint32_t pack2h(float x, float y) {
    __half hx = __float2half_rn(x), hy = __float2half_rn(y);
    return (uint32_t)__half_as_ushort(hx) | ((uint32_t)__half_as_ushort(hy) << 16);
}

__device__ __forceinline__ void split2f(float x, float y, uint32_t& h, uint32_t& l) {
    __half hx = __float2half_rn(x);
    __half hy = __float2half_rn(y);
    __half lx = __float2half_rn(x - __half2float(hx));
    __half ly = __float2half_rn(y - __half2float(hy));
    h = (uint32_t)__half_as_ushort(hx) | ((uint32_t)__half_as_ushort(hy) << 16);
    l = (uint32_t)__half_as_ushort(lx) | ((uint32_t)__half_as_ushort(ly) << 16);
}

__device__ __forceinline__ void cpa16(uint32_t dst, const void* src, bool v) {
    int sz = v ? 16 : 0;
    asm volatile("cp.async.cg.shared.global [%0], [%1], 16, %2;\n"
                 :: "r"(dst), "l"(src), "r"(sz));
}
#define CP_COMMIT() asm volatile("cp.async.commit_group;\n" ::: "memory")
#define CP_WAIT(n)  asm volatile("cp.async.wait_group %0;\n" :: "n"(n) : "memory")

// physical smem offset of logical (row, 16B-unit) under XOR swizzle, 64B rows
__device__ __forceinline__ uint32_t swz(int row, int unit) {
    return (uint32_t)(row * 64 + ((unit ^ ((row & 7) >> 1)) << 4));
}

// ---------------- init + splits --------------------------------------------------
__global__ void init_kernel() {
    if (threadIdx.x < E_EXP) g_cnt[threadIdx.x] = 0;
}

// scheduler: compact active (expert, m-tile) pairs
__global__ void sched_kernel() {
    if (threadIdx.x == 0) {
        int np = 0;
        for (int e = 0; e < E_EXP; e++) {
            int tiles = (g_cnt[e] + 127) >> 7;
            for (int m = 0; m < tiles; m++) {
                g_pair_e[np] = e;
                g_pair_mt[np] = m;
                np++;
            }
        }
        g_npairs = np;
        g_wk1 = 0;
        g_wk2 = 0;
    }
}

// one weight tensor -> fp16 hi
__global__ void splith_kernel(const float4* __restrict__ src,
                              uint2* __restrict__ dh, int n4) {
    int i = blockIdx.x * blockDim.x + threadIdx.x;
    if (i >= n4) return;
    float4 v = src[i];
    dh[i] = make_uint2(pack2h(v.x, v.y), pack2h(v.z, v.w));
}

// activations: fp16 hi + lo
__global__ void splitx_kernel(const float4* __restrict__ src,
                              uint2* __restrict__ dh, uint2* __restrict__ dl,
                              int n4) {
    int i = blockIdx.x * blockDim.x + threadIdx.x;
    if (i >= n4) return;
    float4 v = src[i];
    uint32_t h0, l0, h1, l1;
    split2f(v.x, v.y, h0, l0);
    split2f(v.z, v.w, h1, l1);
    dh[i] = make_uint2(h0, h1);
    dl[i] = make_uint2(l0, l1);
}

// ---------------- router: 8 tokens per block -----------------------------------
__global__ void __launch_bounds__(128) router_kernel(
    const float* __restrict__ x, const float* __restrict__ rw,
    const float* __restrict__ rb) {
    __shared__ float xs[RTOK][DMODEL];
    __shared__ float logits[RTOK][E_EXP];

    int t0 = blockIdx.x * RTOK;
    int tid = threadIdx.x;

    const float4* x4 = (const float4*)(x + (size_t)t0 * DMODEL);
    float4* xs4 = (float4*)&xs[0][0];
    for (int i = tid; i < RTOK * DMODEL / 4; i += 128) xs4[i] = x4[i];
    __syncthreads();

    int warp = tid >> 5, lane = tid & 31;
    for (int p = warp; p < RTOK * E_EXP; p += 4) {
        int tok = p >> 4, e = p & 15;
        const float* w = rw + (size_t)e * DMODEL;
        float s = 0.f;
        for (int k = lane; k < DMODEL; k += 32) s += xs[tok][k] * w[k];
        #pragma unroll
        for (int o = 16; o; o >>= 1) s += __shfl_xor_sync(0xffffffffu, s, o);
        if (lane == 0) logits[tok][e] = s + rb[e];
    }
    __syncthreads();

    if (tid < RTOK) {
        int t = t0 + tid;
        float m = -1e30f;
        #pragma unroll
        for (int e = 0; e < E_EXP; e++) m = fmaxf(m, logits[tid][e]);
        float p[E_EXP];
        #pragma unroll
        for (int e = 0; e < E_EXP; e++) p[e] = __expf(logits[tid][e] - m);
        int e0 = 0;
        #pragma unroll
        for (int e = 1; e < E_EXP; e++) if (p[e] > p[e0]) e0 = e;
        int e1 = (e0 == 0) ? 1 : 0;
        #pragma unroll
        for (int e = 0; e < E_EXP; e++) {
            if (e == e0 || e == e1) continue;
            if (p[e] > p[e1]) e1 = e;
        }
        float s01 = p[e0] + p[e1];
        float c0 = p[e0] / s01, c1 = p[e1] / s01;
        int pos0 = atomicAdd(&g_cnt[e0], 1);
        g_list[e0 * TMAX + pos0] = t * 2 + 0;
        int pos1 = atomicAdd(&g_cnt[e1], 1);
        g_list[e1 * TMAX + pos1] = t * 2 + 1;
        g_tok_e[2 * t + 0] = e0; g_tok_c[2 * t + 0] = c0;
        g_tok_e[2 * t + 1] = e1; g_tok_c[2 * t + 1] = c1;
    }
}

// stage byte layout (64B rows, swizzled):
//   gemm1 (128x64):  Ah 0 (8KB) | Al 8192 | W1h 16384 (4KB) | W3h 20480
//   gemm2 (128x128): Ah 0 (8KB) | Al 8192 | Wh 16384 (8KB)
#define G1_STG 24576
#define G1_SMEM (3 * G1_STG)
#define G2_STG 24576
#define G2_SMEM (3 * G2_STG)

// =====================  GEMM1: H = silu(Xg W1^T) * (Xg W3^T)  ==================
__global__ void __launch_bounds__(256, 2) gemm1_tc() {
    extern __shared__ __align__(128) char smem[];
    __shared__ int rows[128];
    __shared__ int s_w;

    int tid = threadIdx.x;
    int lane = tid & 31, warp = tid >> 5;
    int warp_m = warp & 3, warp_n = warp >> 2;     // 4x2 warp grid
    int g = lane >> 2, t4 = lane & 3;

    uint32_t sb = smem_u32(smem);
    int rowA0 = warp_m * 32 + (lane & 15);
    int u0a = lane >> 4;
    int rowB0 = warp_n * 32 + (lane & 7) + ((lane & 16) ? 8 : 0);
    int u0b = (lane >> 3) & 1;

    // tile-invariant: A dst offsets, ldsm offsets
    int rA[4], grpA[4], hfA[4];
    uint32_t dstA[4];
    #pragma unroll
    for (int i = 0; i < 4; i++) {
        int idx = tid + 256 * i;
        rA[i] = idx >> 3;
        int sub = idx & 7;
        grpA[i] = sub & 3;
        hfA[i] = sub >> 2;
        dstA[i] = (uint32_t)(hfA[i] * 8192) + swz(rA[i], grpA[i]);
    }
    int wrow = tid >> 2, wgrp = tid & 3;
    uint32_t dstW1 = 16384 + swz(wrow, wgrp);
    uint32_t dstW3 = 20480 + swz(wrow, wgrp);

    uint32_t aoff[2][2], boff[2][2];
    #pragma unroll
    for (int ks = 0; ks < 2; ks++) {
        #pragma unroll
        for (int mt = 0; mt < 2; mt++)
            aoff[ks][mt] = swz(rowA0 + mt * 16, u0a + 2 * ks);
        #pragma unroll
        for (int ntp = 0; ntp < 2; ntp++)
            boff[ks][ntp] = 16384u + swz(rowB0 + ntp * 16, u0b + 2 * ks);
    }

    const int NS = DMODEL / BK;   // 32

    for (;;) {
        __syncthreads();                   // protect rows[] from prior epilogue
        if (tid == 0) s_w = atomicAdd(&g_wk1, 1);
        __syncthreads();
        int w = s_w;
        int np = g_npairs;
        if (w >= np * 32) break;
        int pair = w >> 5;
        int e = g_pair_e[pair];
        int mt0 = g_pair_mt[pair];
        int n0 = (w & 31) * 64;
        int c = g_cnt[e];

        if (tid < 128) {
            int pos = mt0 * 128 + tid;
            rows[tid] = (pos < c) ? g_list[e * TMAX + pos] : -1;
        }
        __syncthreads();

        // per-tile copy sources
        const __half* srcA[4];
        bool vA[4];
        #pragma unroll
        for (int i = 0; i < 4; i++) {
            int pid = rows[rA[i]];
            const __half* base = hfA[i] ? g_xl : g_xh;
            vA[i] = (pid >= 0);
            srcA[i] = vA[i] ? (base + (size_t)(pid >> 1) * DMODEL + grpA[i] * 8) : base;
        }
        const size_t wbase = ((size_t)e * DFF + n0) * DMODEL;
        const __half* srcW1 = g_w1h + wbase + (size_t)wrow * DMODEL + wgrp * 8;
        const __half* srcW3 = g_w3h + wbase + (size_t)wrow * DMODEL + wgrp * 8;

        float acc1[2][4][4], acc3[2][4][4];
        #pragma unroll
        for (int i = 0; i < 2; i++)
            #pragma unroll
            for (int j = 0; j < 4; j++)
                #pragma unroll
                for (int k = 0; k < 4; k++) { acc1[i][j][k] = 0.f; acc3[i][j][k] = 0.f; }

        auto ISSUE = [&](int s) {
            uint32_t stb = sb + (uint32_t)(s % 3) * G1_STG;
            int off = s * BK;
            #pragma unroll
            for (int i = 0; i < 4; i++) cpa16(stb + dstA[i], srcA[i] + off, vA[i]);
            cpa16(stb + dstW1, srcW1 + off, true);
            cpa16(stb + dstW3, srcW3 + off, true);
        };

        ISSUE(0); CP_COMMIT();
        ISSUE(1); CP_COMMIT();
        for (int s = 0; s < NS; s++) {
            CP_WAIT(1);
            __syncthreads();
            if (s + 2 < NS) ISSUE(s + 2);
            CP_COMMIT();

            uint32_t stb = sb + (uint32_t)(s % 3) * G1_STG;
            #pragma unroll
            for (int ks = 0; ks < 2; ks++) {
                uint32_t ah[2][4], al[2][4];
                #pragma unroll
                for (int mt = 0; mt < 2; mt++) {
                    uint32_t ao = stb + aoff[ks][mt];
                    ldsm4(ah[mt], ao);
                    ldsm4(al[mt], ao + 8192);
                }
                #pragma unroll
                for (int ntp = 0; ntp < 2; ntp++) {
                    uint32_t b1[4], b3[4];
                    uint32_t bo = stb + boff[ks][ntp];
                    ldsm4(b1, bo);
                    ldsm4(b3, bo + 4096);
                    #pragma unroll
                    for (int half = 0; half < 2; half++) {
                        int nt = ntp * 2 + half;
                        #pragma unroll
                        for (int mt = 0; mt < 2; mt++) {
                            mma_f16(acc1[mt][nt], ah[mt], b1[half * 2], b1[half * 2 + 1]);
                            mma_f16(acc1[mt][nt], al[mt], b1[half * 2], b1[half * 2 + 1]);
                            mma_f16(acc3[mt][nt], ah[mt], b3[half * 2], b3[half * 2 + 1]);
                            mma_f16(acc3[mt][nt], al[mt], b3[half * 2], b3[half * 2 + 1]);
                        }
                    }
                }
            }
        }

        // epilogue: silu(acc1) * acc3 -> fp16 split -> g_Hh / g_Hl
        #pragma unroll
        for (int mt = 0; mt < 2; mt++) {
            int rl = warp_m * 32 + mt * 16 + g;
            int pid0 = rows[rl], pid1 = rows[rl + 8];
            #pragma unroll
            for (int nt = 0; nt < 4; nt++) {
                int col = n0 + warp_n * 32 + nt * 8 + 2 * t4;
                if (pid0 >= 0) {
                    float z0 = acc1[mt][nt][0], z1 = acc1[mt][nt][1];
                    float o0 = z0 / (1.f + __expf(-z0)) * acc3[mt][nt][0];
                    float o1 = z1 / (1.f + __expf(-z1)) * acc3[mt][nt][1];
                    uint32_t h, l;
                    split2f(o0, o1, h, l);
                    *(uint32_t*)(g_Hh + (size_t)pid0 * DFF + col) = h;
                    *(uint32_t*)(g_Hl + (size_t)pid0 * DFF + col) = l;
                }
                if (pid1 >= 0) {
                    float z2 = acc1[mt][nt][2], z3 = acc1[mt][nt][3];
                    float o2 = z2 / (1.f + __expf(-z2)) * acc3[mt][nt][2];
                    float o3 = z3 / (1.f + __expf(-z3)) * acc3[mt][nt][3];
                    uint32_t h, l;
                    split2f(o2, o3, h, l);
                    *(uint32_t*)(g_Hh + (size_t)pid1 * DFF + col) = h;
                    *(uint32_t*)(g_Hl + (size_t)pid1 * DFF + col) = l;
                }
            }
        }
    }
}

// =====================  GEMM2: Y = Hg W2^T  (128x128 tile) =====================
__global__ void __launch_bounds__(256, 2) gemm2_tc() {
    extern __shared__ __align__(128) char smem[];
    __shared__ int rows[128];
    __shared__ int s_w;

    int tid = threadIdx.x;
    int lane = tid & 31, warp = tid >> 5;
    int warp_m = warp & 3, warp_n = warp >> 2;     // warp tile 32x64
    int g = lane >> 2, t4 = lane & 3;

    uint32_t sb = smem_u32(smem);
    int rowA0 = warp_m * 32 + (lane & 15);
    int u0a = lane >> 4;
    int rowB0 = warp_n * 64 + (lane & 7) + ((lane & 16) ? 8 : 0);
    int u0b = (lane >> 3) & 1;

    int rA[4], grpA[4], hfA[4];
    uint32_t dstA[4];
    #pragma unroll
    for (int i = 0; i < 4; i++) {
        int idx = tid + 256 * i;
        rA[i] = idx >> 3;
        int sub = idx & 7;
        grpA[i] = sub & 3;
        hfA[i] = sub >> 2;
        dstA[i] = (uint32_t)(hfA[i] * 8192) + swz(rA[i], grpA[i]);
    }
    int wrowA[2], wgrpA[2];
    uint32_t dstW[2];
    #pragma unroll
    for (int i = 0; i < 2; i++) {
        int idx = tid + 256 * i;
        wrowA[i] = idx >> 2;
        wgrpA[i] = idx & 3;
        dstW[i] = 16384u + swz(wrowA[i], wgrpA[i]);
    }

    uint32_t aoff[2][2], boff[2][4];
    #pragma unroll
    for (int ks = 0; ks < 2; ks++) {
        #pragma unroll
        for (int mt = 0; mt < 2; mt++)
            aoff[ks][mt] = swz(rowA0 + mt * 16, u0a + 2 * ks);
        #pragma unroll
        for (int ntp = 0; ntp < 4; ntp++)
            boff[ks][ntp] = 16384u + swz(rowB0 + ntp * 16, u0b + 2 * ks);
    }

    const int NS = DFF / BK;   // 64

    for (;;) {
        __syncthreads();
        if (tid == 0) s_w = atomicAdd(&g_wk2, 1);
        __syncthreads();
        int w = s_w;
        int np = g_npairs;
        if (w >= np * 8) break;
        int pair = w >> 3;
        int e = g_pair_e[pair];
        int mt0 = g_pair_mt[pair];
        int n0 = (w & 7) * 128;
        int c = g_cnt[e];

        if (tid < 128) {
            int pos = mt0 * 128 + tid;
            rows[tid] = (pos < c) ? g_list[e * TMAX + pos] : -1;
        }
        __syncthreads();

        const __half* srcA[4];
        bool vA[4];
        #pragma unroll
        for (int i = 0; i < 4; i++) {
            int pid = rows[rA[i]];
            const __half* base = hfA[i] ? g_Hl : g_Hh;
            vA[i] = (pid >= 0);
            srcA[i] = vA[i] ? (base + (size_t)pid * DFF + grpA[i] * 8) : base;
        }
        const size_t wbase = ((size_t)e * DMODEL + n0) * DFF;
        const __half* srcW[2];
        #pragma unroll
        for (int i = 0; i < 2; i++)
            srcW[i] = g_w2h + wbase + (size_t)wrowA[i] * DFF + wgrpA[i] * 8;

        float acc[2][8][4];
        #pragma unroll
        for (int i = 0; i < 2; i++)
            #pragma unroll
            for (int j = 0; j < 8; j++)
                #pragma unroll
                for (int k = 0; k < 4; k++) acc[i][j][k] = 0.f;

        auto ISSUE = [&](int s) {
            uint32_t stb = sb + (uint32_t)(s % 3) * G2_STG;
            int off = s * BK;
            #pragma unroll
            for (int i = 0; i < 4; i++) cpa16(stb + dstA[i], srcA[i] + off, vA[i]);
            #pragma unroll
            for (int i = 0; i < 2; i++) cpa16(stb + dstW[i], srcW[i] + off, true);
        };

        ISSUE(0); CP_COMMIT();
        ISSUE(1); CP_COMMIT();
        for (int s = 0; s < NS; s++) {
            CP_WAIT(1);
            __syncthreads();
            if (s + 2 < NS) ISSUE(s + 2);
            CP_COMMIT();

            uint32_t stb = sb + (uint32_t)(s % 3) * G2_STG;
            #pragma unroll
            for (int ks = 0; ks < 2; ks++) {
                uint32_t ah[2][4], al[2][4];
                #pragma unroll
                for (int mt = 0; mt < 2; mt++) {
                    uint32_t ao = stb + aoff[ks][mt];
                    ldsm4(ah[mt], ao);
                    ldsm4(al[mt], ao + 8192);
                }
                #pragma unroll
                for (int ntp = 0; ntp < 4; ntp++) {
                    uint32_t bh[4];
                    ldsm4(bh, stb + boff[ks][ntp]);
                    #pragma unroll
                    for (int half = 0; half < 2; half++) {
                        int nt = ntp * 2 + half;
                        #pragma unroll
                        for (int mt = 0; mt < 2; mt++) {
                            mma_f16(acc[mt][nt], ah[mt], bh[half * 2], bh[half * 2 + 1]);
                            mma_f16(acc[mt][nt], al[mt], bh[half * 2], bh[half * 2 + 1]);
                        }
                    }
                }
            }
        }

        #pragma unroll
        for (int mt = 0; mt < 2; mt++) {
            int rl = warp_m * 32 + mt * 16 + g;
            int pid0 = rows[rl], pid1 = rows[rl + 8];
            #pragma unroll
            for (int nt = 0; nt < 8; nt++) {
                int col = n0 + warp_n * 64 + nt * 8 + 2 * t4;
                if (pid0 >= 0)
                    *(float2*)(g_Y + (size_t)pid0 * DMODEL + col) =
                        make_float2(acc[mt][nt][0], acc[mt][nt][1]);
                if (pid1 >= 0)
                    *(float2*)(g_Y + (size_t)pid1 * DMODEL + col) =
                        make_float2(acc[mt][nt][2], acc[mt][nt][3]);
            }
        }
    }
}

// ---------------- per-token dual LayerNorm + combine ---------------------------
__global__ void __launch_bounds__(256) ln2_kernel(
    const float* __restrict__ ln_g, const float* __restrict__ ln_b,
    float* __restrict__ out) {
    int t = blockIdx.x;
    int e0 = g_tok_e[2 * t], e1 = g_tok_e[2 * t + 1];
    float c0 = g_tok_c[2 * t], c1 = g_tok_c[2 * t + 1];
    const float* y0 = g_Y + (size_t)(2 * t) * DMODEL;
    const float* y1 = g_Y + (size_t)(2 * t + 1) * DMODEL;

    __shared__ float red[16];
    int lane = threadIdx.x & 31, warp = threadIdx.x >> 5;

    float v0[4], v1[4];
    float s0 = 0.f, s1 = 0.f;
    #pragma unroll
    for (int i = 0; i < 4; i++) {
        int col = threadIdx.x + i * 256;
        v0[i] = y0[col]; s0 += v0[i];
        v1[i] = y1[col]; s1 += v1[i];
    }
    #pragma unroll
    for (int o = 16; o; o >>= 1) {
        s0 += __shfl_xor_sync(0xffffffffu, s0, o);
        s1 += __shfl_xor_sync(0xffffffffu, s1, o);
    }
    if (lane == 0) { red[warp] = s0; red[8 + warp] = s1; }
    __syncthreads();
    float m0 = 0.f, m1 = 0.f;
    #pragma unroll
    for (int i = 0; i < 8; i++) { m0 += red[i]; m1 += red[8 + i]; }
    float mu0 = m0 * (1.f / DMODEL), mu1 = m1 * (1.f / DMODEL);
    __syncthreads();

    float q0 = 0.f, q1 = 0.f;
    #pragma unroll
    for (int i = 0; i < 4; i++) {
        float d0 = v0[i] - mu0; q0 += d0 * d0;
        float d1 = v1[i] - mu1; q1 += d1 * d1;
    }
    #pragma unroll
    for (int o = 16; o; o >>= 1) {
        q0 += __shfl_xor_sync(0xffffffffu, q0, o);
        q1 += __shfl_xor_sync(0xffffffffu, q1, o);
    }
    if (lane == 0) { red[warp] = q0; red[8 + warp] = q1; }
    __syncthreads();
    float t0 = 0.f, t1 = 0.f;
    #pragma unroll
    for (int i = 0; i < 8; i++) { t0 += red[i]; t1 += red[8 + i]; }
    float rstd0 = rsqrtf(t0 * (1.f / DMODEL) + LN_EPS);
    float rstd1 = rsqrtf(t1 * (1.f / DMODEL) + LN_EPS);

    const float* ga = ln_g + (size_t)e0 * DMODEL;
    const float* ba = ln_b + (size_t)e0 * DMODEL;
    const float* gb = ln_g + (size_t)e1 * DMODEL;
    const float* bb = ln_b + (size_t)e1 * DMODEL;
    #pragma unroll
    for (int i = 0; i < 4; i++) {
        int col = threadIdx.x + i * 256;
        float yn0 = (v0[i] - mu0) * rstd0 * ga[col] + ba[col];
        float yn1 = (v1[i] - mu1) * rstd1 * gb[col] + bb[col];
        out[(size_t)t * DMODEL + col] = c0 * yn0 + c1 * yn1;
    }
}

// ---------------- launch --------------------------------------------------------
extern "C" void kernel_launch(void* const* d_in, const int* in_sizes, int n_in,
                              void* d_out, int out_size) {
    const float* x  = (const float*)d_in[0];
    const float* rw = (const float*)d_in[1];
    const float* rb = (const float*)d_in[2];
    const float* w1 = (const float*)d_in[3];
    const float* w2 = (const float*)d_in[4];
    const float* w3 = (const float*)d_in[5];
    const float* lg = (const float*)d_in[6];
    const float* lb = (const float*)d_in[7];
    float* out = (float*)d_out;

    int T = in_sizes[0] / DMODEL;   // 4096

    static bool init_done = false;
    static cudaStream_t sB;
    static cudaEvent_t evRoot, evA, evB;
    if (!init_done) {
        cudaFuncSetAttribute(gemm1_tc, cudaFuncAttributeMaxDynamicSharedMemorySize, G1_SMEM);
        cudaFuncSetAttribute(gemm2_tc, cudaFuncAttributeMaxDynamicSharedMemorySize, G2_SMEM);
        cudaFuncSetAttribute(gemm1_tc, cudaFuncAttributePreferredSharedMemoryCarveout,
                             cudaSharedmemCarveoutMaxShared);
        cudaFuncSetAttribute(gemm2_tc, cudaFuncAttributePreferredSharedMemoryCarveout,
                             cudaSharedmemCarveoutMaxShared);
        cudaStreamCreateWithFlags(&sB, cudaStreamNonBlocking);
        cudaEventCreateWithFlags(&evRoot, cudaEventDisableTiming);
        cudaEventCreateWithFlags(&evA, cudaEventDisableTiming);
        cudaEventCreateWithFlags(&evB, cudaEventDisableTiming);
        init_done = true;
    }

    __half *w1h, *w3h, *w2h, *xh, *xl;
    cudaGetSymbolAddress((void**)&w1h, g_w1h);
    cudaGetSymbolAddress((void**)&w3h, g_w3h);
    cudaGetSymbolAddress((void**)&w2h, g_w2h);
    cudaGetSymbolAddress((void**)&xh,  g_xh);
    cudaGetSymbolAddress((void**)&xl,  g_xl);

    int nw4 = (int)((size_t)E_EXP * DFF * DMODEL / 4);   // 8388608
    int nx4 = (int)((size_t)T * DMODEL / 4);             // 1048576

    cudaEventRecord(evRoot, 0);
    cudaStreamWaitEvent(sB, evRoot, 0);

    splith_kernel<<<nw4 / 256, 256, 0, sB>>>((const float4*)w1, (uint2*)w1h, nw4);
    splith_kernel<<<nw4 / 256, 256, 0, sB>>>((const float4*)w3, (uint2*)w3h, nw4);
    cudaEventRecord(evA, sB);
    splith_kernel<<<nw4 / 256, 256, 0, sB>>>((const float4*)w2, (uint2*)w2h, nw4);
    cudaEventRecord(evB, sB);

    init_kernel<<<1, 32>>>();
    splitx_kernel<<<(nx4 + 255) / 256, 256>>>((const float4*)x, (uint2*)xh, (uint2*)xl, nx4);
    router_kernel<<<T / RTOK, 128>>>(x, rw, rb);
    sched_kernel<<<1, 32>>>();

    cudaStreamWaitEvent(0, evA, 0);
    gemm1_tc<<<PGRID, 256, G1_SMEM>>>();

    cudaStreamWaitEvent(0, evB, 0);
    gemm2_tc<<<PGRID, 256, G2_SMEM>>>();

    ln2_kernel<<<T, 256>>>(lg, lb, out);
}

// round 17
// speedup vs baseline: 1.0106x; 1.0106x over previous
#include <cuda_runtime.h>
#include <cuda_fp16.h>
#include <cstdint>

// Problem constants
#define E_EXP 16
#define DMODEL 1024
#define DFF 2048
#define TMAX 4096
#define LN_EPS 1e-5f

#define BK 64          // fp32 elements per K-stage (two 32-col halves)
#define RTOK 8         // tokens per router block

// ---------------- scratch (device globals) ------------------------------------
__device__ int   g_cnt[E_EXP];
__device__ int   g_list[E_EXP * TMAX];             // pid = token*2 + slot
__device__ int   g_tok_e[2 * TMAX];
__device__ float g_tok_c[2 * TMAX];
__device__ float g_Y[(size_t)2 * TMAX * DMODEL];   // [pid][D]

// fp16 tensors: activations split hi/lo, weights hi only
__device__ __align__(16) __half g_xh[(size_t)TMAX * DMODEL];
__device__ __align__(16) __half g_xl[(size_t)TMAX * DMODEL];
__device__ __align__(16) __half g_w1h[(size_t)E_EXP * DFF * DMODEL];
__device__ __align__(16) __half g_w3h[(size_t)E_EXP * DFF * DMODEL];
__device__ __align__(16) __half g_w2h[(size_t)E_EXP * DMODEL * DFF];
__device__ __align__(16) __half g_Hh[(size_t)2 * TMAX * DFF];
__device__ __align__(16) __half g_Hl[(size_t)2 * TMAX * DFF];

// ---------------- helpers -------------------------------------------------------
__device__ __forceinline__ uint32_t smem_u32(const void* p) {
    uint32_t a;
    asm("{ .reg .u64 t; cvta.to.shared.u64 t, %1; cvt.u32.u64 %0, t; }" : "=r"(a) : "l"(p));
    return a;
}

__device__ __forceinline__ void mma_f16(float* c, const uint32_t* a,
                                        uint32_t b0, uint32_t b1) {
    asm volatile(
        "mma.sync.aligned.m16n8k16.row.col.f32.f16.f16.f32 "
        "{%0,%1,%2,%3}, {%4,%5,%6,%7}, {%8,%9}, {%0,%1,%2,%3};\n"
        : "+f"(c[0]), "+f"(c[1]), "+f"(c[2]), "+f"(c[3])
        : "r"(a[0]), "r"(a[1]), "r"(a[2]), "r"(a[3]), "r"(b0), "r"(b1));
}

__device__ __forceinline__ void ldsm4(uint32_t* r, uint32_t a) {
    asm volatile("ldmatrix.sync.aligned.m8n8.x4.shared.b16 {%0,%1,%2,%3}, [%4];"
        : "=r"(r[0]), "=r"(r[1]), "=r"(r[2]), "=r"(r[3]) : "r"(a));
}

__device__ __forceinline__ uint32_t pack2h(float x, float y) {
    __half hx = __float2half_rn(x), hy = __float2half_rn(y);
    return (uint32_t)__half_as_ushort(hx) | ((uint32_t)__half_as_ushort(hy) << 16);
}

__device__ __forceinline__ void split2f(float x, float y, uint32_t& h, uint32_t& l) {
    __half hx = __float2half_rn(x);
    __half hy = __float2half_rn(y);
    __half lx = __float2half_rn(x - __half2float(hx));
    __half ly = __float2half_rn(y - __half2float(hy));
    h = (uint32_t)__half_as_ushort(hx) | ((uint32_t)__half_as_ushort(hy) << 16);
    l = (uint32_t)__half_as_ushort(lx) | ((uint32_t)__half_as_ushort(ly) << 16);
}

__device__ __forceinline__ void cpa16(uint32_t dst, const void* src, bool v) {
    int sz = v ? 16 : 0;
    asm volatile("cp.async.cg.shared.global [%0], [%1], 16, %2;\n"
                 :: "r"(dst), "l"(src), "r"(sz));
}
#define CP_COMMIT() asm volatile("cp.async.commit_group;\n" ::: "memory")
#define CP_WAIT(n)  asm volatile("cp.async.wait_group %0;\n" :: "n"(n) : "memory")

// physical smem offset of logical (row, 16B-unit) under XOR swizzle, 64B rows
__device__ __forceinline__ uint32_t swz(int row, int unit) {
    return (uint32_t)(row * 64 + ((unit ^ ((row & 7) >> 1)) << 4));
}

// ---------------- init + splits --------------------------------------------------
__global__ void init_kernel() {
    if (threadIdx.x < E_EXP) g_cnt[threadIdx.x] = 0;
}

// one weight tensor -> fp16 hi
__global__ void splith_kernel(const float4* __restrict__ src,
                              uint2* __restrict__ dh, int n4) {
    int i = blockIdx.x * blockDim.x + threadIdx.x;
    if (i >= n4) return;
    float4 v = src[i];
    dh[i] = make_uint2(pack2h(v.x, v.y), pack2h(v.z, v.w));
}

// activations: fp16 hi + lo
__global__ void splitx_kernel(const float4* __restrict__ src,
                              uint2* __restrict__ dh, uint2* __restrict__ dl,
                              int n4) {
    int i = blockIdx.x * blockDim.x + threadIdx.x;
    if (i >= n4) return;
    float4 v = src[i];
    uint32_t h0, l0, h1, l1;
    split2f(v.x, v.y, h0, l0);
    split2f(v.z, v.w, h1, l1);
    dh[i] = make_uint2(h0, h1);
    dl[i] = make_uint2(l0, l1);
}

// ---------------- router: 8 tokens per block -----------------------------------
__global__ void __launch_bounds__(128) router_kernel(
    const float* __restrict__ x, const float* __restrict__ rw,
    const float* __restrict__ rb) {
    __shared__ float xs[RTOK][DMODEL];
    __shared__ float logits[RTOK][E_EXP];

    int t0 = blockIdx.x * RTOK;
    int tid = threadIdx.x;

    const float4* x4 = (const float4*)(x + (size_t)t0 * DMODEL);
    float4* xs4 = (float4*)&xs[0][0];
    for (int i = tid; i < RTOK * DMODEL / 4; i += 128) xs4[i] = x4[i];
    __syncthreads();

    int warp = tid >> 5, lane = tid & 31;
    for (int p = warp; p < RTOK * E_EXP; p += 4) {
        int tok = p >> 4, e = p & 15;
        const float* w = rw + (size_t)e * DMODEL;
        float s = 0.f;
        for (int k = lane; k < DMODEL; k += 32) s += xs[tok][k] * w[k];
        #pragma unroll
        for (int o = 16; o; o >>= 1) s += __shfl_xor_sync(0xffffffffu, s, o);
        if (lane == 0) logits[tok][e] = s + rb[e];
    }
    __syncthreads();

    if (tid < RTOK) {
        int t = t0 + tid;
        float m = -1e30f;
        #pragma unroll
        for (int e = 0; e < E_EXP; e++) m = fmaxf(m, logits[tid][e]);
        float p[E_EXP];
        #pragma unroll
        for (int e = 0; e < E_EXP; e++) p[e] = __expf(logits[tid][e] - m);
        int e0 = 0;
        #pragma unroll
        for (int e = 1; e < E_EXP; e++) if (p[e] > p[e0]) e0 = e;
        int e1 = (e0 == 0) ? 1 : 0;
        #pragma unroll
        for (int e = 0; e < E_EXP; e++) {
            if (e == e0 || e == e1) continue;
            if (p[e] > p[e1]) e1 = e;
        }
        float s01 = p[e0] + p[e1];
        float c0 = p[e0] / s01, c1 = p[e1] / s01;
        int pos0 = atomicAdd(&g_cnt[e0], 1);
        g_list[e0 * TMAX + pos0] = t * 2 + 0;
        int pos1 = atomicAdd(&g_cnt[e1], 1);
        g_list[e1 * TMAX + pos1] = t * 2 + 1;
        g_tok_e[2 * t + 0] = e0; g_tok_c[2 * t + 0] = c0;
        g_tok_e[2 * t + 1] = e1; g_tok_c[2 * t + 1] = c1;
    }
}

// stage byte layout (64B rows, swizzled; kh = K half):
//   gemm1 (128x64):  Ah kh*8192 [0,16K) | Al 16384+kh*8192 [16K,32K)
//                    W1h 32768+kh*4096 [32K,40K) | W3h 40960+kh*4096 [40K,48K)
//   gemm2 (128x128): Ah kh*8192 | Al 16384+kh*8192 | Wh 32768+kh*8192 [32K,48K)
#define G1_STG 49152
#define G1_SMEM (2 * G1_STG)
#define G2_STG 49152
#define G2_SMEM (2 * G2_STG)

// =====================  GEMM1: H = silu(Xg W1^T) * (Xg W3^T)  ==================
__global__ void __launch_bounds__(256, 2) gemm1_tc() {
    int e = blockIdx.z;
    int c = g_cnt[e];
    int mt0 = blockIdx.x;
    if (mt0 * 128 >= c) return;
    int n0 = blockIdx.y * 64;

    extern __shared__ __align__(128) char smem[];
    __shared__ int rows[128];

    int tid = threadIdx.x;
    if (tid < 128) {
        int pos = mt0 * 128 + tid;
        rows[tid] = (pos < c) ? g_list[e * TMAX + pos] : -1;
    }
    __syncthreads();

    int lane = tid & 31, warp = tid >> 5;
    int warp_m = warp & 3, warp_n = warp >> 2;     // 4x2 warp grid
    int g = lane >> 2, t4 = lane & 3;

    uint32_t sb = smem_u32(smem);
    int rowA0 = warp_m * 32 + (lane & 15);
    int u0a = lane >> 4;
    int rowB0 = warp_n * 32 + (lane & 7) + ((lane & 16) ? 8 : 0);
    int u0b = (lane >> 3) & 1;

    // ---- A copy params: 8 copies/thread, same (sub) decode for all ----
    int r0a = tid >> 4;
    int subA = tid & 15;
    int hfA = subA >> 3, uA = subA & 7, khA = uA >> 2, grpA = uA & 3;
    uint32_t dstA0 = (uint32_t)(hfA * 16384 + khA * 8192) + swz(r0a, grpA);
    const __half* baseA = (hfA ? g_xl : g_xh) + khA * 32 + grpA * 8;
    int pidA[8];
    #pragma unroll
    for (int i = 0; i < 8; i++) pidA[i] = rows[r0a + 16 * i];

    // ---- W copy params: 4 copies/thread (W1 r, W1 r+32, W3 r, W3 r+32) ----
    int r0w = tid >> 3;
    int uW = tid & 7, khW = uW >> 2, grpW = uW & 3;
    const size_t wbase = ((size_t)e * DFF + n0) * DMODEL;
    const __half* srcW1 = g_w1h + wbase + (size_t)r0w * DMODEL + khW * 32 + grpW * 8;
    const __half* srcW3 = g_w3h + wbase + (size_t)r0w * DMODEL + khW * 32 + grpW * 8;
    uint32_t dstW1a = 32768u + (uint32_t)(khW * 4096) + swz(r0w, grpW);
    uint32_t dstW3a = dstW1a + 8192u;

    // ---- ldsm base offsets (row-periodic: +16 rows = +1024B) ----
    uint32_t aoffk[2], boffk[2];
    #pragma unroll
    for (int ks2 = 0; ks2 < 2; ks2++) {
        aoffk[ks2] = swz(rowA0, u0a + 2 * ks2);
        boffk[ks2] = swz(rowB0, u0b + 2 * ks2);
    }

    float acc1[2][4][4], acc3[2][4][4];
    #pragma unroll
    for (int i = 0; i < 2; i++)
        #pragma unroll
        for (int j = 0; j < 4; j++)
            #pragma unroll
            for (int k = 0; k < 4; k++) { acc1[i][j][k] = 0.f; acc3[i][j][k] = 0.f; }

    auto ISSUE = [&](int s) {
        uint32_t stb = sb + (uint32_t)(s & 1) * G1_STG;
        const __half* ab = baseA + s * BK;
        #pragma unroll
        for (int i = 0; i < 8; i++) {
            bool v = (pidA[i] >= 0);
            const __half* sp = v ? (ab + (size_t)(pidA[i] >> 1) * DMODEL) : baseA;
            cpa16(stb + dstA0 + i * 1024, sp, v);
        }
        const __half* w1p = srcW1 + s * BK;
        const __half* w3p = srcW3 + s * BK;
        cpa16(stb + dstW1a, w1p, true);
        cpa16(stb + dstW1a + 2048, w1p + 32 * DMODEL, true);
        cpa16(stb + dstW3a, w3p, true);
        cpa16(stb + dstW3a + 2048, w3p + 32 * DMODEL, true);
    };

    const int NS = DMODEL / BK;   // 16
    ISSUE(0); CP_COMMIT();
    for (int s = 0; s < NS; s++) {
        CP_WAIT(0);
        __syncthreads();
        if (s + 1 < NS) { ISSUE(s + 1); CP_COMMIT(); }

        uint32_t stb = sb + (uint32_t)(s & 1) * G1_STG;
        #pragma unroll
        for (int ks = 0; ks < 4; ks++) {
            const int kh = ks >> 1, ks2 = ks & 1;
            uint32_t abase = stb + kh * 8192 + aoffk[ks2];
            uint32_t ah[2][4], al[2][4];
            #pragma unroll
            for (int mt = 0; mt < 2; mt++) {
                ldsm4(ah[mt], abase + mt * 1024);
                ldsm4(al[mt], abase + 16384 + mt * 1024);
            }
            uint32_t bbase = stb + 32768 + kh * 4096 + boffk[ks2];
            #pragma unroll
            for (int ntp = 0; ntp < 2; ntp++) {
                uint32_t b1[4], b3[4];
                ldsm4(b1, bbase + ntp * 1024);
                ldsm4(b3, bbase + 8192 + ntp * 1024);
                #pragma unroll
                for (int half = 0; half < 2; half++) {
                    int nt = ntp * 2 + half;
                    #pragma unroll
                    for (int mt = 0; mt < 2; mt++) {
                        mma_f16(acc1[mt][nt], ah[mt], b1[half * 2], b1[half * 2 + 1]);
                        mma_f16(acc1[mt][nt], al[mt], b1[half * 2], b1[half * 2 + 1]);
                        mma_f16(acc3[mt][nt], ah[mt], b3[half * 2], b3[half * 2 + 1]);
                        mma_f16(acc3[mt][nt], al[mt], b3[half * 2], b3[half * 2 + 1]);
                    }
                }
            }
        }
    }

    // epilogue: silu(acc1) * acc3 -> fp16 split -> g_Hh / g_Hl
    #pragma unroll
    for (int mt = 0; mt < 2; mt++) {
        int rl = warp_m * 32 + mt * 16 + g;
        int pid0 = rows[rl], pid1 = rows[rl + 8];
        #pragma unroll
        for (int nt = 0; nt < 4; nt++) {
            int col = n0 + warp_n * 32 + nt * 8 + 2 * t4;
            if (pid0 >= 0) {
                float z0 = acc1[mt][nt][0], z1 = acc1[mt][nt][1];
                float o0 = z0 / (1.f + __expf(-z0)) * acc3[mt][nt][0];
                float o1 = z1 / (1.f + __expf(-z1)) * acc3[mt][nt][1];
                uint32_t h, l;
                split2f(o0, o1, h, l);
                *(uint32_t*)(g_Hh + (size_t)pid0 * DFF + col) = h;
                *(uint32_t*)(g_Hl + (size_t)pid0 * DFF + col) = l;
            }
            if (pid1 >= 0) {
                float z2 = acc1[mt][nt][2], z3 = acc1[mt][nt][3];
                float o2 = z2 / (1.f + __expf(-z2)) * acc3[mt][nt][2];
                float o3 = z3 / (1.f + __expf(-z3)) * acc3[mt][nt][3];
                uint32_t h, l;
                split2f(o2, o3, h, l);
                *(uint32_t*)(g_Hh + (size_t)pid1 * DFF + col) = h;
                *(uint32_t*)(g_Hl + (size_t)pid1 * DFF + col) = l;
            }
        }
    }
}

// =====================  GEMM2: Y = Hg W2^T  (128x128 tile) =====================
__global__ void __launch_bounds__(256, 2) gemm2_tc() {
    int e = blockIdx.z;
    int c = g_cnt[e];
    int mt0 = blockIdx.x;
    if (mt0 * 128 >= c) return;
    int n0 = blockIdx.y * 128;

    extern __shared__ __align__(128) char smem[];
    __shared__ int rows[128];

    int tid = threadIdx.x;
    if (tid < 128) {
        int pos = mt0 * 128 + tid;
        rows[tid] = (pos < c) ? g_list[e * TMAX + pos] : -1;
    }
    __syncthreads();

    int lane = tid & 31, warp = tid >> 5;
    int warp_m = warp & 3, warp_n = warp >> 2;     // warp tile 32x64
    int g = lane >> 2, t4 = lane & 3;

    uint32_t sb = smem_u32(smem);
    int rowA0 = warp_m * 32 + (lane & 15);
    int u0a = lane >> 4;
    int rowB0 = warp_n * 64 + (lane & 7) + ((lane & 16) ? 8 : 0);
    int u0b = (lane >> 3) & 1;

    // ---- A copy params ----
    int r0a = tid >> 4;
    int subA = tid & 15;
    int hfA = subA >> 3, uA = subA & 7, khA = uA >> 2, grpA = uA & 3;
    uint32_t dstA0 = (uint32_t)(hfA * 16384 + khA * 8192) + swz(r0a, grpA);
    const __half* baseA = (hfA ? g_Hl : g_Hh) + khA * 32 + grpA * 8;
    int pidA[8];
    #pragma unroll
    for (int i = 0; i < 8; i++) pidA[i] = rows[r0a + 16 * i];

    // ---- W copy params: 4 copies/thread (rows r0w + 32i) ----
    int r0w = tid >> 3;
    int uW = tid & 7, khW = uW >> 2, grpW = uW & 3;
    const size_t wbase = ((size_t)e * DMODEL + n0) * DFF;
    const __half* srcW = g_w2h + wbase + (size_t)r0w * DFF + khW * 32 + grpW * 8;
    uint32_t dstW0 = 32768u + (uint32_t)(khW * 8192) + swz(r0w, grpW);

    uint32_t aoffk[2], boffk[2];
    #pragma unroll
    for (int ks2 = 0; ks2 < 2; ks2++) {
        aoffk[ks2] = swz(rowA0, u0a + 2 * ks2);
        boffk[ks2] = swz(rowB0, u0b + 2 * ks2);
    }

    float acc[2][8][4];
    #pragma unroll
    for (int i = 0; i < 2; i++)
        #pragma unroll
        for (int j = 0; j < 8; j++)
            #pragma unroll
            for (int k = 0; k < 4; k++) acc[i][j][k] = 0.f;

    auto ISSUE = [&](int s) {
        uint32_t stb = sb + (uint32_t)(s & 1) * G2_STG;
        const __half* ab = baseA + s * BK;
        #pragma unroll
        for (int i = 0; i < 8; i++) {
            bool v = (pidA[i] >= 0);
            const __half* sp = v ? (ab + (size_t)pidA[i] * DFF) : baseA;
            cpa16(stb + dstA0 + i * 1024, sp, v);
        }
        const __half* wp = srcW + s * BK;
        #pragma unroll
        for (int i = 0; i < 4; i++)
            cpa16(stb + dstW0 + i * 2048, wp + (size_t)(32 * i) * DFF, true);
    };

    const int NS = DFF / BK;   // 32
    ISSUE(0); CP_COMMIT();
    for (int s = 0; s < NS; s++) {
        CP_WAIT(0);
        __syncthreads();
        if (s + 1 < NS) { ISSUE(s + 1); CP_COMMIT(); }

        uint32_t stb = sb + (uint32_t)(s & 1) * G2_STG;
        #pragma unroll
        for (int ks = 0; ks < 4; ks++) {
            const int kh = ks >> 1, ks2 = ks & 1;
            uint32_t abase = stb + kh * 8192 + aoffk[ks2];
            uint32_t ah[2][4], al[2][4];
            #pragma unroll
            for (int mt = 0; mt < 2; mt++) {
                ldsm4(ah[mt], abase + mt * 1024);
                ldsm4(al[mt], abase + 16384 + mt * 1024);
            }
            uint32_t bbase = stb + 32768 + kh * 8192 + boffk[ks2];
            #pragma unroll
            for (int ntp = 0; ntp < 4; ntp++) {
                uint32_t bh[4];
                ldsm4(bh, bbase + ntp * 1024);
                #pragma unroll
                for (int half = 0; half < 2; half++) {
                    int nt = ntp * 2 + half;
                    #pragma unroll
                    for (int mt = 0; mt < 2; mt++) {
                        mma_f16(acc[mt][nt], ah[mt], bh[half * 2], bh[half * 2 + 1]);
                        mma_f16(acc[mt][nt], al[mt], bh[half * 2], bh[half * 2 + 1]);
                    }
                }
            }
        }
    }

    #pragma unroll
    for (int mt = 0; mt < 2; mt++) {
        int rl = warp_m * 32 + mt * 16 + g;
        int pid0 = rows[rl], pid1 = rows[rl + 8];
        #pragma unroll
        for (int nt = 0; nt < 8; nt++) {
            int col = n0 + warp_n * 64 + nt * 8 + 2 * t4;
            if (pid0 >= 0)
                *(float2*)(g_Y + (size_t)pid0 * DMODEL + col) =
                    make_float2(acc[mt][nt][0], acc[mt][nt][1]);
            if (pid1 >= 0)
                *(float2*)(g_Y + (size_t)pid1 * DMODEL + col) =
                    make_float2(acc[mt][nt][2], acc[mt][nt][3]);
        }
    }
}

// ---------------- per-token dual LayerNorm + combine ---------------------------
__global__ void __launch_bounds__(256) ln2_kernel(
    const float* __restrict__ ln_g, const float* __restrict__ ln_b,
    float* __restrict__ out) {
    int t = blockIdx.x;
    int e0 = g_tok_e[2 * t], e1 = g_tok_e[2 * t + 1];
    float c0 = g_tok_c[2 * t], c1 = g_tok_c[2 * t + 1];
    const float* y0 = g_Y + (size_t)(2 * t) * DMODEL;
    const float* y1 = g_Y + (size_t)(2 * t + 1) * DMODEL;

    __shared__ float red[16];
    int lane = threadIdx.x & 31, warp = threadIdx.x >> 5;

    float v0[4], v1[4];
    float s0 = 0.f, s1 = 0.f;
    #pragma unroll
    for (int i = 0; i < 4; i++) {
        int col = threadIdx.x + i * 256;
        v0[i] = y0[col]; s0 += v0[i];
        v1[i] = y1[col]; s1 += v1[i];
    }
    #pragma unroll
    for (int o = 16; o; o >>= 1) {
        s0 += __shfl_xor_sync(0xffffffffu, s0, o);
        s1 += __shfl_xor_sync(0xffffffffu, s1, o);
    }
    if (lane == 0) { red[warp] = s0; red[8 + warp] = s1; }
    __syncthreads();
    float m0 = 0.f, m1 = 0.f;
    #pragma unroll
    for (int i = 0; i < 8; i++) { m0 += red[i]; m1 += red[8 + i]; }
    float mu0 = m0 * (1.f / DMODEL), mu1 = m1 * (1.f / DMODEL);
    __syncthreads();

    float q0 = 0.f, q1 = 0.f;
    #pragma unroll
    for (int i = 0; i < 4; i++) {
        float d0 = v0[i] - mu0; q0 += d0 * d0;
        float d1 = v1[i] - mu1; q1 += d1 * d1;
    }
    #pragma unroll
    for (int o = 16; o; o >>= 1) {
        q0 += __shfl_xor_sync(0xffffffffu, q0, o);
        q1 += __shfl_xor_sync(0xffffffffu, q1, o);
    }
    if (lane == 0) { red[warp] = q0; red[8 + warp] = q1; }
    __syncthreads();
    float t0 = 0.f, t1 = 0.f;
    #pragma unroll
    for (int i = 0; i < 8; i++) { t0 += red[i]; t1 += red[8 + i]; }
    float rstd0 = rsqrtf(t0 * (1.f / DMODEL) + LN_EPS);
    float rstd1 = rsqrtf(t1 * (1.f / DMODEL) + LN_EPS);

    const float* ga = ln_g + (size_t)e0 * DMODEL;
    const float* ba = ln_b + (size_t)e0 * DMODEL;
    const float* gb = ln_g + (size_t)e1 * DMODEL;
    const float* bb = ln_b + (size_t)e1 * DMODEL;
    #pragma unroll
    for (int i = 0; i < 4; i++) {
        int col = threadIdx.x + i * 256;
        float yn0 = (v0[i] - mu0) * rstd0 * ga[col] + ba[col];
        float yn1 = (v1[i] - mu1) * rstd1 * gb[col] + bb[col];
        out[(size_t)t * DMODEL + col] = c0 * yn0 + c1 * yn1;
    }
}

// ---------------- launch --------------------------------------------------------
extern "C" void kernel_launch(void* const* d_in, const int* in_sizes, int n_in,
                              void* d_out, int out_size) {
    const float* x  = (const float*)d_in[0];
    const float* rw = (const float*)d_in[1];
    const float* rb = (const float*)d_in[2];
    const float* w1 = (const float*)d_in[3];
    const float* w2 = (const float*)d_in[4];
    const float* w3 = (const float*)d_in[5];
    const float* lg = (const float*)d_in[6];
    const float* lb = (const float*)d_in[7];
    float* out = (float*)d_out;

    int T = in_sizes[0] / DMODEL;   // 4096

    static bool init_done = false;
    static cudaStream_t sB;
    static cudaEvent_t evRoot, evA, evB;
    if (!init_done) {
        cudaFuncSetAttribute(gemm1_tc, cudaFuncAttributeMaxDynamicSharedMemorySize, G1_SMEM);
        cudaFuncSetAttribute(gemm2_tc, cudaFuncAttributeMaxDynamicSharedMemorySize, G2_SMEM);
        cudaFuncSetAttribute(gemm1_tc, cudaFuncAttributePreferredSharedMemoryCarveout,
                             cudaSharedmemCarveoutMaxShared);
        cudaFuncSetAttribute(gemm2_tc, cudaFuncAttributePreferredSharedMemoryCarveout,
                             cudaSharedmemCarveoutMaxShared);
        cudaStreamCreateWithFlags(&sB, cudaStreamNonBlocking);
        cudaEventCreateWithFlags(&evRoot, cudaEventDisableTiming);
        cudaEventCreateWithFlags(&evA, cudaEventDisableTiming);
        cudaEventCreateWithFlags(&evB, cudaEventDisableTiming);
        init_done = true;
    }

    __half *w1h, *w3h, *w2h, *xh, *xl;
    cudaGetSymbolAddress((void**)&w1h, g_w1h);
    cudaGetSymbolAddress((void**)&w3h, g_w3h);
    cudaGetSymbolAddress((void**)&w2h, g_w2h);
    cudaGetSymbolAddress((void**)&xh,  g_xh);
    cudaGetSymbolAddress((void**)&xl,  g_xl);

    int nw4 = (int)((size_t)E_EXP * DFF * DMODEL / 4);   // 8388608
    int nx4 = (int)((size_t)T * DMODEL / 4);             // 1048576

    cudaEventRecord(evRoot, 0);
    cudaStreamWaitEvent(sB, evRoot, 0);

    splith_kernel<<<nw4 / 256, 256, 0, sB>>>((const float4*)w1, (uint2*)w1h, nw4);
    splith_kernel<<<nw4 / 256, 256, 0, sB>>>((const float4*)w3, (uint2*)w3h, nw4);
    cudaEventRecord(evA, sB);
    splith_kernel<<<nw4 / 256, 256, 0, sB>>>((const float4*)w2, (uint2*)w2h, nw4);
    cudaEventRecord(evB, sB);

    init_kernel<<<1, 32>>>();
    splitx_kernel<<<(nx4 + 255) / 256, 256>>>((const float4*)x, (uint2*)xh, (uint2*)xl, nx4);
    router_kernel<<<T / RTOK, 128>>>(x, rw, rb);

    cudaStreamWaitEvent(0, evA, 0);
    dim3 g1((T + 127) / 128, DFF / 64, E_EXP);
    gemm1_tc<<<g1, 256, G1_SMEM>>>();

    cudaStreamWaitEvent(0, evB, 0);
    dim3 g2((T + 127) / 128, DMODEL / 128, E_EXP);
    gemm2_tc<<<g2, 256, G2_SMEM>>>();

    ln2_kernel<<<T, 256>>>(lg, lb, out);
}